// round 6
// baseline (speedup 1.0000x reference)
#include <cuda_runtime.h>
#include <math.h>

#define Bn 2
#define Tt 4
#define NC 3
#define NK 16
#define Hh 180
#define Ww 320
#define HW (Hh*Ww)
#define CIN_D (Tt*NK)   // 64
#define OUT_C 48
#define SCALE 4

#define LTW 64
#define LTH 16
#define SPW 68
#define SPH 18
#define SPA (SPH*SPW)

typedef unsigned long long ull;

// Scratch (no cudaMalloc allowed)
__device__ float g_hs[Bn*CIN_D*HW];
__device__ float g_c[Bn*NK*HW];
__device__ float g_om[Bn*27*HW];
__device__ float g_def[Bn*NK*HW];

__device__ __forceinline__ float sig_(float v) {
    return __fdividef(1.f, 1.f + __expf(-v));
}
__device__ __forceinline__ float tanh_(float v) {
    float e = __expf(2.f * v);
    return 1.f - __fdividef(2.f, e + 1.f);
}

// ---- packed f32x2 helpers ----
__device__ __forceinline__ ull pack2(float lo, float hi) {
    ull r;
    asm("mov.b64 %0, {%1, %2};" : "=l"(r) : "f"(lo), "f"(hi));
    return r;
}
__device__ __forceinline__ void ffma2(ull& d, ull a, ull b) {
    asm("fma.rn.f32x2 %0, %1, %2, %0;" : "+l"(d) : "l"(a), "l"(b));
}
__device__ __forceinline__ float2 unpack2(ull v) {
    float2 f;
    asm("mov.b64 {%0, %1}, %2;" : "=f"(f.x), "=f"(f.y) : "l"(v));
    return f;
}

__device__ __forceinline__ void cp_async4(float* dst_smem, const float* src) {
    unsigned d = (unsigned)__cvta_generic_to_shared(dst_smem);
    asm volatile("cp.async.ca.shared.global [%0], [%1], 4;" :: "r"(d), "l"(src));
}
#define CP_COMMIT() asm volatile("cp.async.commit_group;" ::: "memory")
#define CP_WAIT0()  asm volatile("cp.async.wait_group 0;" ::: "memory")

// async-stage one channel patch (halo + zero pad)
__device__ __forceinline__ void stage_patch_async(float* dst, const float* src,
                                                  int bx, int by, int tid)
{
    #pragma unroll
    for (int i = tid; i < SPA; i += 256) {
        int pr = i / SPW, pc = i - pr * SPW;
        int gy = by - 1 + pr, gx = bx - 1 + pc;
        if (pc < 66 && gy >= 0 && gy < Hh && gx >= 0 && gx < Ww)
            cp_async4(dst + i, src + gy * Ww + gx);
        else
            dst[i] = 0.f;
    }
}

// one channel's 3x3 conv into packed acc2[16][2] (2 px per lane-pair)
__device__ __forceinline__ void conv_accum2(ull acc2[16][2], const float* patch,
                                            const float* wc, int tx, int ty)
{
    #pragma unroll
    for (int tr = 0; tr < 3; tr++) {
        const float4* rp = (const float4*)(patch + (ty + tr) * SPW + tx * 4);
        float4 a = rp[0], bq = rp[1];
        float v[6] = {a.x, a.y, a.z, a.w, bq.x, bq.y};
        #pragma unroll
        for (int tc = 0; tc < 3; tc++) {
            ull q0 = pack2(v[tc],     v[tc + 1]);
            ull q1 = pack2(v[tc + 2], v[tc + 3]);
            const float4* w4 = (const float4*)(wc + (tr * 3 + tc) * 16);
            #pragma unroll
            for (int q = 0; q < 4; q++) {
                float4 w = w4[q];
                ull wx = pack2(w.x, w.x);
                ull wy = pack2(w.y, w.y);
                ull wz = pack2(w.z, w.z);
                ull ww = pack2(w.w, w.w);
                ffma2(acc2[q*4+0][0], q0, wx); ffma2(acc2[q*4+0][1], q1, wx);
                ffma2(acc2[q*4+1][0], q0, wy); ffma2(acc2[q*4+1][1], q1, wy);
                ffma2(acc2[q*4+2][0], q0, wz); ffma2(acc2[q*4+2][1], q1, wz);
                ffma2(acc2[q*4+3][0], q0, ww); ffma2(acc2[q*4+3][1], q1, ww);
            }
        }
    }
}

// ---------------------------------------------------------------------------
// ConvLSTM step. block (16,16); thread = 4 px, 16 outputs (4 k x 4 gates)
// blockIdx.z = b*4 + kg. cp.async pipelined, CH=4, packed f32x2 math.
// ---------------------------------------------------------------------------
__global__ __launch_bounds__(256, 2)
void lstm_step_kernel(const float* __restrict__ X,
                      const float* __restrict__ lw,
                      const float* __restrict__ lb,
                      const float* __restrict__ Wci,
                      const float* __restrict__ Wcf,
                      const float* __restrict__ Wco,
                      int t)
{
    __shared__ float sw[19 * 9 * 16];
    __shared__ float sp[2][4 * SPA];
    __shared__ float sb[16];

    const int tx = threadIdx.x, ty = threadIdx.y;
    const int tid = ty * 16 + tx;
    const int bz = blockIdx.z;
    const int b = bz >> 2, kg = bz & 3;
    const int bx = blockIdx.x * LTW, by = blockIdx.y * LTH;
    const int x0 = bx + tx * 4, y = by + ty;

    for (int i = tid; i < 19 * 144; i += 256) {
        int lo = i / 171, rest = i - lo * 171;
        int row = (lo >> 2) * NK + kg * 4 + (lo & 3);
        sw[rest * 16 + lo] = lw[row * 171 + rest];
    }
    if (tid < 16)
        sb[tid] = lb[(tid >> 2) * NK + kg * 4 + (tid & 3)];

    const int ncin = (t == 0) ? NC : (NC + NK);
    const int nb = (ncin + 3) >> 2;

    #define LSTM_SRC(c) ((c) < NC \
        ? (X + (((size_t)b * Tt + t) * NC + (c)) * HW) \
        : (g_hs + ((size_t)b * CIN_D + (t - 1) * NK + ((c) - NC)) * HW))

    #pragma unroll
    for (int cc = 0; cc < 4; cc++)
        if (cc < ncin) stage_patch_async(sp[0] + cc * SPA, LSTM_SRC(cc), bx, by, tid);
    CP_COMMIT();

    __syncthreads();   // sb/sw visible

    ull acc2[16][2];
    #pragma unroll
    for (int lo = 0; lo < 16; lo++) {
        ull bv = pack2(sb[lo], sb[lo]);
        acc2[lo][0] = bv; acc2[lo][1] = bv;
    }

    for (int cb = 0; cb < nb; cb++) {
        int cur = cb & 1;
        CP_WAIT0();
        __syncthreads();
        if (cb + 1 < nb) {
            int cn = (cb + 1) * 4;
            #pragma unroll
            for (int cc = 0; cc < 4; cc++)
                if (cn + cc < ncin)
                    stage_patch_async(sp[cur ^ 1] + cc * SPA, LSTM_SRC(cn + cc), bx, by, tid);
        }
        CP_COMMIT();
        int c0 = cb * 4;
        #pragma unroll
        for (int cc = 0; cc < 4; cc++)
            if (c0 + cc < ncin)
                conv_accum2(acc2, sp[cur] + cc * SPA, sw + (c0 + cc) * 144, tx, ty);
    }
    #undef LSTM_SRC

    if (y < Hh) {
        const int p = y * Ww + x0;
        float accf[16][4];
        #pragma unroll
        for (int lo = 0; lo < 16; lo++) {
            float2 u0 = unpack2(acc2[lo][0]), u1 = unpack2(acc2[lo][1]);
            accf[lo][0] = u0.x; accf[lo][1] = u0.y;
            accf[lo][2] = u1.x; accf[lo][3] = u1.y;
        }
        #pragma unroll
        for (int kk = 0; kk < 4; kk++) {
            int k = kg * 4 + kk;
            float ci4[4], cf4[4], co4[4], cp4[4], cn4[4], h4[4];
            *(float4*)ci4 = *(const float4*)(Wci + k * HW + p);
            *(float4*)cf4 = *(const float4*)(Wcf + k * HW + p);
            *(float4*)co4 = *(const float4*)(Wco + k * HW + p);
            if (t == 0) {
                #pragma unroll
                for (int px = 0; px < 4; px++) cp4[px] = 0.f;
            } else {
                *(float4*)cp4 = *(const float4*)(g_c + ((size_t)b * NK + k) * HW + p);
            }
            #pragma unroll
            for (int px = 0; px < 4; px++) {
                float cprev = cp4[px];
                float i_ = sig_(accf[kk][px]      + ci4[px] * cprev);
                float f_ = sig_(accf[4 + kk][px]  + cf4[px] * cprev);
                float cn = f_ * cprev + i_ * tanh_(accf[8 + kk][px]);
                float o_ = sig_(accf[12 + kk][px] + co4[px] * cn);
                cn4[px] = cn;
                h4[px] = o_ * tanh_(cn);
            }
            *(float4*)(g_c + ((size_t)b * NK + k) * HW + p) = *(float4*)cn4;
            *(float4*)(g_hs + ((size_t)b * CIN_D + t * NK + k) * HW + p) = *(float4*)h4;
        }
    }
}

// ---------------------------------------------------------------------------
// Offset+mask conv 64 -> 27. blockIdx.z = b*2 + half. f32x2 packed.
// ---------------------------------------------------------------------------
__global__ __launch_bounds__(256, 2)
void offmask_kernel(const float* __restrict__ off_w,
                    const float* __restrict__ off_b,
                    const float* __restrict__ mod_w,
                    const float* __restrict__ mod_b)
{
    __shared__ float sw[16 * 576];
    __shared__ float sp[2][4 * SPA];
    __shared__ float sb[16];

    const int tx = threadIdx.x, ty = threadIdx.y;
    const int tid = ty * 16 + tx;
    const int bz = blockIdx.z;
    const int b = bz >> 1, half = bz & 1;
    const int base = half * 16;
    const int count = half ? 11 : 16;
    const int bx = blockIdx.x * LTW, by = blockIdx.y * LTH;
    const int x0 = bx + tx * 4, y = by + ty;

    for (int i = tid; i < 16 * 576; i += 256) {
        int lo = i / 576, rest = i - lo * 576;
        int oc = base + lo;
        float v = 0.f;
        if (oc < 18) v = off_w[(size_t)oc * 576 + rest];
        else if (oc < 27) v = mod_w[(size_t)(oc - 18) * 576 + rest];
        sw[rest * 16 + lo] = v;
    }
    if (tid < 16) {
        int oc = base + tid;
        sb[tid] = (oc < 18) ? off_b[oc] : (oc < 27 ? mod_b[oc - 18] : 0.f);
    }

    const float* xb = g_hs + (size_t)b * CIN_D * HW;

    #pragma unroll
    for (int cc = 0; cc < 4; cc++)
        stage_patch_async(sp[0] + cc * SPA, xb + (size_t)cc * HW, bx, by, tid);
    CP_COMMIT();

    __syncthreads();

    ull acc2[16][2];
    #pragma unroll
    for (int lo = 0; lo < 16; lo++) {
        ull bv = pack2(sb[lo], sb[lo]);
        acc2[lo][0] = bv; acc2[lo][1] = bv;
    }

    for (int cb = 0; cb < 16; cb++) {
        int cur = cb & 1;
        CP_WAIT0();
        __syncthreads();
        if (cb + 1 < 16) {
            int cn = (cb + 1) * 4;
            #pragma unroll
            for (int cc = 0; cc < 4; cc++)
                stage_patch_async(sp[cur ^ 1] + cc * SPA, xb + (size_t)(cn + cc) * HW, bx, by, tid);
        }
        CP_COMMIT();
        int c0 = cb * 4;
        #pragma unroll
        for (int cc = 0; cc < 4; cc++)
            conv_accum2(acc2, sp[cur] + cc * SPA, sw + (c0 + cc) * 144, tx, ty);
    }

    if (y < Hh) {
        const int p = y * Ww + x0;
        #pragma unroll
        for (int lo = 0; lo < 16; lo++) {
            if (lo >= count) break;
            int oc = base + lo;
            float2 u0 = unpack2(acc2[lo][0]), u1 = unpack2(acc2[lo][1]);
            float o4[4] = {u0.x, u0.y, u1.x, u1.y};
            if (oc >= 18) {
                #pragma unroll
                for (int px = 0; px < 4; px++) o4[px] = 2.f * sig_(o4[px]);
            }
            *(float4*)(g_om + ((size_t)b * 27 + oc) * HW + p) = *(float4*)o4;
        }
    }
}

// ---------------------------------------------------------------------------
// Modulated deformable conv. block (32,8), 1 px/thread, 16 outputs (8 pairs).
// ---------------------------------------------------------------------------
__global__ __launch_bounds__(256)
void deform_kernel(const float* __restrict__ def_w,
                   const float* __restrict__ def_b)
{
    __shared__ float swd[NK * CIN_D * 9];
    __shared__ float sb[NK];

    const int bx = blockIdx.x * 32, by = blockIdx.y * 8;
    const int b = blockIdx.z;
    const int tx = threadIdx.x, ty = threadIdx.y;
    const int tid = ty * 32 + tx;

    for (int i = tid; i < NK * CIN_D * 9; i += 256) {
        int o = i / 576, rest = i - o * 576;
        swd[rest * 16 + o] = def_w[i];
    }
    if (tid < NK) sb[tid] = def_b[tid];
    __syncthreads();

    const int x = bx + tx, y = by + ty;
    if (y >= Hh) return;
    const int p = y * Ww + x;

    const float* xb = g_hs + (size_t)b * CIN_D * HW;
    const float* om = g_om + (size_t)b * 27 * HW;

    ull acc2[8];
    #pragma unroll
    for (int q = 0; q < 8; q++) acc2[q] = pack2(sb[2*q], sb[2*q+1]);

    #pragma unroll
    for (int j = 0; j < 9; j++) {
        int ky = j / 3, kx = j - ky * 3;
        float dy = om[(2 * j) * HW + p];
        float dx = om[(2 * j + 1) * HW + p];
        float m  = om[(18 + j) * HW + p];
        float py = (float)(y - 1 + ky) + dy;
        float px_ = (float)(x - 1 + kx) + dx;
        float y0f = floorf(py), x0f = floorf(px_);
        float wy = py - y0f, wx = px_ - x0f;
        int y0 = (int)y0f, x0 = (int)x0f;
        int y1 = y0 + 1,   x1 = x0 + 1;
        float vy0 = (y0 >= 0 && y0 < Hh) ? 1.f : 0.f;
        float vy1 = (y1 >= 0 && y1 < Hh) ? 1.f : 0.f;
        float vx0 = (x0 >= 0 && x0 < Ww) ? 1.f : 0.f;
        float vx1 = (x1 >= 0 && x1 < Ww) ? 1.f : 0.f;
        int y0c = min(max(y0, 0), Hh - 1), y1c = min(max(y1, 0), Hh - 1);
        int x0c = min(max(x0, 0), Ww - 1), x1c = min(max(x1, 0), Ww - 1);
        float w00 = (1.f - wy) * (1.f - wx) * vy0 * vx0 * m;
        float w01 = (1.f - wy) * wx         * vy0 * vx1 * m;
        float w10 = wy * (1.f - wx)         * vy1 * vx0 * m;
        float w11 = wy * wx                 * vy1 * vx1 * m;
        int o00 = y0c * Ww + x0c, o01 = y0c * Ww + x1c;
        int o10 = y1c * Ww + x0c, o11 = y1c * Ww + x1c;

        #pragma unroll 4
        for (int c = 0; c < CIN_D; c++) {
            const float* pc_ = xb + (size_t)c * HW;
            float s = w00 * pc_[o00] + w01 * pc_[o01]
                    + w10 * pc_[o10] + w11 * pc_[o11];
            ull ss = pack2(s, s);
            const ulonglong2* w2 = (const ulonglong2*)(swd + (c * 9 + j) * 16);
            ulonglong2 wa = w2[0], wb = w2[1], wc2 = w2[2], wd = w2[3];
            ffma2(acc2[0], ss, wa.x); ffma2(acc2[1], ss, wa.y);
            ffma2(acc2[2], ss, wb.x); ffma2(acc2[3], ss, wb.y);
            ffma2(acc2[4], ss, wc2.x); ffma2(acc2[5], ss, wc2.y);
            ffma2(acc2[6], ss, wd.x); ffma2(acc2[7], ss, wd.y);
        }
    }

    #pragma unroll
    for (int q = 0; q < 8; q++) {
        float2 u = unpack2(acc2[q]);
        g_def[((size_t)b * NK + 2*q    ) * HW + p] = u.x;
        g_def[((size_t)b * NK + 2*q + 1) * HW + p] = u.y;
    }
}

// ---------------------------------------------------------------------------
// Output conv 16 -> 48 (3 groups of 16) + pixel shuffle + clip. f32x2 packed.
// ---------------------------------------------------------------------------
__global__ __launch_bounds__(256, 2)
void outconv_kernel(const float* __restrict__ out_w,
                    const float* __restrict__ out_b,
                    float* __restrict__ out)
{
    __shared__ float sw[16 * 144];
    __shared__ float sp[2][4 * SPA];
    __shared__ float sb[16];

    const int tx = threadIdx.x, ty = threadIdx.y;
    const int tid = ty * 16 + tx;
    const int bz = blockIdx.z;
    const int b = bz / 3, g3 = bz - b * 3;
    const int base = g3 * 16;
    const int bx = blockIdx.x * LTW, by = blockIdx.y * LTH;
    const int x0 = bx + tx * 4, y = by + ty;

    for (int i = tid; i < 16 * 144; i += 256) {
        int lo = i / 144, rest = i - lo * 144;
        sw[rest * 16 + lo] = out_w[(size_t)(base + lo) * 144 + rest];
    }
    if (tid < 16) sb[tid] = out_b[base + tid];

    const float* xb = g_def + (size_t)b * NK * HW;

    #pragma unroll
    for (int cc = 0; cc < 4; cc++)
        stage_patch_async(sp[0] + cc * SPA, xb + (size_t)cc * HW, bx, by, tid);
    CP_COMMIT();

    __syncthreads();

    ull acc2[16][2];
    #pragma unroll
    for (int lo = 0; lo < 16; lo++) {
        ull bv = pack2(sb[lo], sb[lo]);
        acc2[lo][0] = bv; acc2[lo][1] = bv;
    }

    for (int cb = 0; cb < 4; cb++) {
        int cur = cb & 1;
        CP_WAIT0();
        __syncthreads();
        if (cb + 1 < 4) {
            int cn = (cb + 1) * 4;
            #pragma unroll
            for (int cc = 0; cc < 4; cc++)
                stage_patch_async(sp[cur ^ 1] + cc * SPA, xb + (size_t)(cn + cc) * HW, bx, by, tid);
        }
        CP_COMMIT();
        int c0 = cb * 4;
        #pragma unroll
        for (int cc = 0; cc < 4; cc++)
            conv_accum2(acc2, sp[cur] + cc * SPA, sw + (c0 + cc) * 144, tx, ty);
    }

    if (y < Hh) {
        #pragma unroll
        for (int lo = 0; lo < 16; lo++) {
            int oc = base + lo;
            int cch = oc >> 4, rem = oc & 15;
            int r1 = rem >> 2, r2 = rem & 3;
            float2 u0 = unpack2(acc2[lo][0]), u1 = unpack2(acc2[lo][1]);
            float o4[4] = {u0.x, u0.y, u1.x, u1.y};
            #pragma unroll
            for (int px = 0; px < 4; px++) {
                float val = fminf(fmaxf(o4[px], 0.f), 255.f);
                size_t oi = (((size_t)b * NC + cch) * (Hh * SCALE) + (y * SCALE + r1))
                            * (size_t)(Ww * SCALE) + ((x0 + px) * SCALE + r2);
                out[oi] = val;
            }
        }
    }
}

// ---------------------------------------------------------------------------
extern "C" void kernel_launch(void* const* d_in, const int* in_sizes, int n_in,
                              void* d_out, int out_size)
{
    const float* X      = (const float*)d_in[0];
    const float* lstm_w = (const float*)d_in[1];
    const float* lstm_b = (const float*)d_in[2];
    const float* W_ci   = (const float*)d_in[3];
    const float* W_cf   = (const float*)d_in[4];
    const float* W_co   = (const float*)d_in[5];
    const float* off_w  = (const float*)d_in[6];
    const float* off_b  = (const float*)d_in[7];
    const float* mod_w  = (const float*)d_in[8];
    const float* mod_b  = (const float*)d_in[9];
    const float* def_w  = (const float*)d_in[10];
    const float* def_b  = (const float*)d_in[11];
    const float* out_w  = (const float*)d_in[12];
    const float* out_b  = (const float*)d_in[13];
    float* out = (float*)d_out;

    dim3 blk16(16, 16);
    dim3 grid_lstm(Ww / LTW, (Hh + LTH - 1) / LTH, Bn * 4);
    dim3 grid_om(Ww / LTW, (Hh + LTH - 1) / LTH, Bn * 2);
    dim3 grid_oc(Ww / LTW, (Hh + LTH - 1) / LTH, Bn * 3);

    for (int t = 0; t < Tt; t++)
        lstm_step_kernel<<<grid_lstm, blk16>>>(X, lstm_w, lstm_b, W_ci, W_cf, W_co, t);

    offmask_kernel<<<grid_om, blk16>>>(off_w, off_b, mod_w, mod_b);

    dim3 blk32(32, 8);
    dim3 grid_def(Ww / 32, (Hh + 7) / 8, Bn);
    deform_kernel<<<grid_def, blk32>>>(def_w, def_b);

    outconv_kernel<<<grid_oc, blk16>>>(out_w, out_b, out);
}

// round 7
// speedup vs baseline: 1.1001x; 1.1001x over previous
#include <cuda_runtime.h>
#include <math.h>

#define Bn 2
#define Tt 4
#define NC 3
#define NK 16
#define Hh 180
#define Ww 320
#define HW (Hh*Ww)
#define CIN_D (Tt*NK)   // 64
#define OUT_C 48
#define SCALE 4

#define LTW 64
#define LTH 16
#define SPW 68
#define SPH 18
#define SPA (SPH*SPW)

typedef unsigned long long ull;

// Scratch (no cudaMalloc allowed)
__device__ float g_hs[Bn*CIN_D*HW];
__device__ float g_c[Bn*NK*HW];
__device__ float g_om[Bn*27*HW];
__device__ float g_def[Bn*NK*HW];

__device__ __forceinline__ float sig_(float v) {
    return __fdividef(1.f, 1.f + __expf(-v));
}
__device__ __forceinline__ float tanh_(float v) {
    float e = __expf(2.f * v);
    return 1.f - __fdividef(2.f, e + 1.f);
}

// ---- packed f32x2 helpers ----
__device__ __forceinline__ ull pack2(float lo, float hi) {
    ull r;
    asm("mov.b64 %0, {%1, %2};" : "=l"(r) : "f"(lo), "f"(hi));
    return r;
}
__device__ __forceinline__ void ffma2(ull& d, ull a, ull b) {
    asm("fma.rn.f32x2 %0, %1, %2, %0;" : "+l"(d) : "l"(a), "l"(b));
}
__device__ __forceinline__ float2 unpack2(ull v) {
    float2 f;
    asm("mov.b64 {%0, %1}, %2;" : "=f"(f.x), "=f"(f.y) : "l"(v));
    return f;
}

__device__ __forceinline__ void cp_async4(float* dst_smem, const float* src) {
    unsigned d = (unsigned)__cvta_generic_to_shared(dst_smem);
    asm volatile("cp.async.ca.shared.global [%0], [%1], 4;" :: "r"(d), "l"(src));
}
#define CP_COMMIT() asm volatile("cp.async.commit_group;" ::: "memory")
#define CP_WAIT0()  asm volatile("cp.async.wait_group 0;" ::: "memory")

// async-stage one channel patch (halo + zero pad)
__device__ __forceinline__ void stage_patch_async(float* dst, const float* src,
                                                  int bx, int by, int tid)
{
    #pragma unroll
    for (int i = tid; i < SPA; i += 256) {
        int pr = i / SPW, pc = i - pr * SPW;
        int gy = by - 1 + pr, gx = bx - 1 + pc;
        if (pc < 66 && gy >= 0 && gy < Hh && gx >= 0 && gx < Ww)
            cp_async4(dst + i, src + gy * Ww + gx);
        else
            dst[i] = 0.f;
    }
}

// one channel's 3x3 conv; acc2[q][px] = outputs (2q,2q+1) at pixel px.
// Weight pairs come straight out of smem [tap][16] via LDS.128 — no packs.
__device__ __forceinline__ void conv_accum_p(ull acc2[8][4], const float* patch,
                                             const float* wc, int tx, int ty)
{
    #pragma unroll
    for (int tr = 0; tr < 3; tr++) {
        const float4* rp = (const float4*)(patch + (ty + tr) * SPW + tx * 4);
        float4 a = rp[0], bq = rp[1];
        float v[6] = {a.x, a.y, a.z, a.w, bq.x, bq.y};
        ull vv[6];
        #pragma unroll
        for (int j = 0; j < 6; j++) vv[j] = pack2(v[j], v[j]);
        #pragma unroll
        for (int tc = 0; tc < 3; tc++) {
            const ulonglong2* w2 = (const ulonglong2*)(wc + (tr * 3 + tc) * 16);
            ulonglong2 wa = w2[0], wb = w2[1], wcq = w2[2], wd = w2[3];
            ull wp[8] = {wa.x, wa.y, wb.x, wb.y, wcq.x, wcq.y, wd.x, wd.y};
            #pragma unroll
            for (int q = 0; q < 8; q++) {
                #pragma unroll
                for (int px = 0; px < 4; px++)
                    ffma2(acc2[q][px], vv[tc + px], wp[q]);
            }
        }
    }
}

// ---------------------------------------------------------------------------
// ConvLSTM step. block (16,16); thread = 4 px, 16 outputs (4 k x 4 gates)
// blockIdx.z = b*4 + kg. cp.async pipelined, CH=4, f32x2 output-pair packing.
// ---------------------------------------------------------------------------
__global__ __launch_bounds__(256, 2)
void lstm_step_kernel(const float* __restrict__ X,
                      const float* __restrict__ lw,
                      const float* __restrict__ lb,
                      const float* __restrict__ Wci,
                      const float* __restrict__ Wcf,
                      const float* __restrict__ Wco,
                      int t)
{
    __shared__ __align__(16) float sw[19 * 9 * 16];
    __shared__ __align__(16) float sp[2][4 * SPA];
    __shared__ float sb[16];

    const int tx = threadIdx.x, ty = threadIdx.y;
    const int tid = ty * 16 + tx;
    const int bz = blockIdx.z;
    const int b = bz >> 2, kg = bz & 3;
    const int bx = blockIdx.x * LTW, by = blockIdx.y * LTH;
    const int x0 = bx + tx * 4, y = by + ty;

    for (int i = tid; i < 19 * 144; i += 256) {
        int lo = i / 171, rest = i - lo * 171;
        int row = (lo >> 2) * NK + kg * 4 + (lo & 3);
        sw[rest * 16 + lo] = lw[row * 171 + rest];
    }
    if (tid < 16)
        sb[tid] = lb[(tid >> 2) * NK + kg * 4 + (tid & 3)];

    const int ncin = (t == 0) ? NC : (NC + NK);
    const int nb = (ncin + 3) >> 2;

    #define LSTM_SRC(c) ((c) < NC \
        ? (X + (((size_t)b * Tt + t) * NC + (c)) * HW) \
        : (g_hs + ((size_t)b * CIN_D + (t - 1) * NK + ((c) - NC)) * HW))

    #pragma unroll
    for (int cc = 0; cc < 4; cc++)
        if (cc < ncin) stage_patch_async(sp[0] + cc * SPA, LSTM_SRC(cc), bx, by, tid);
    CP_COMMIT();

    __syncthreads();   // sb/sw visible

    ull acc2[8][4];
    #pragma unroll
    for (int q = 0; q < 8; q++) {
        ull bv = pack2(sb[2*q], sb[2*q+1]);
        #pragma unroll
        for (int px = 0; px < 4; px++) acc2[q][px] = bv;
    }

    for (int cb = 0; cb < nb; cb++) {
        int cur = cb & 1;
        CP_WAIT0();
        __syncthreads();
        if (cb + 1 < nb) {
            int cn = (cb + 1) * 4;
            #pragma unroll
            for (int cc = 0; cc < 4; cc++)
                if (cn + cc < ncin)
                    stage_patch_async(sp[cur ^ 1] + cc * SPA, LSTM_SRC(cn + cc), bx, by, tid);
        }
        CP_COMMIT();
        int c0 = cb * 4;
        #pragma unroll
        for (int cc = 0; cc < 4; cc++)
            if (c0 + cc < ncin)
                conv_accum_p(acc2, sp[cur] + cc * SPA, sw + (c0 + cc) * 144, tx, ty);
    }
    #undef LSTM_SRC

    if (y < Hh) {
        const int p = y * Ww + x0;
        float accf[16][4];
        #pragma unroll
        for (int q = 0; q < 8; q++) {
            #pragma unroll
            for (int px = 0; px < 4; px++) {
                float2 u = unpack2(acc2[q][px]);
                accf[2*q][px] = u.x;
                accf[2*q+1][px] = u.y;
            }
        }
        #pragma unroll
        for (int kk = 0; kk < 4; kk++) {
            int k = kg * 4 + kk;
            float ci4[4], cf4[4], co4[4], cp4[4], cn4[4], h4[4];
            *(float4*)ci4 = *(const float4*)(Wci + k * HW + p);
            *(float4*)cf4 = *(const float4*)(Wcf + k * HW + p);
            *(float4*)co4 = *(const float4*)(Wco + k * HW + p);
            if (t == 0) {
                #pragma unroll
                for (int px = 0; px < 4; px++) cp4[px] = 0.f;
            } else {
                *(float4*)cp4 = *(const float4*)(g_c + ((size_t)b * NK + k) * HW + p);
            }
            #pragma unroll
            for (int px = 0; px < 4; px++) {
                float cprev = cp4[px];
                float i_ = sig_(accf[kk][px]      + ci4[px] * cprev);
                float f_ = sig_(accf[4 + kk][px]  + cf4[px] * cprev);
                float cn = f_ * cprev + i_ * tanh_(accf[8 + kk][px]);
                float o_ = sig_(accf[12 + kk][px] + co4[px] * cn);
                cn4[px] = cn;
                h4[px] = o_ * tanh_(cn);
            }
            *(float4*)(g_c + ((size_t)b * NK + k) * HW + p) = *(float4*)cn4;
            *(float4*)(g_hs + ((size_t)b * CIN_D + t * NK + k) * HW + p) = *(float4*)h4;
        }
    }
}

// ---------------------------------------------------------------------------
// Offset+mask conv 64 -> 27. blockIdx.z = b*2 + half. output-pair f32x2.
// ---------------------------------------------------------------------------
__global__ __launch_bounds__(256, 2)
void offmask_kernel(const float* __restrict__ off_w,
                    const float* __restrict__ off_b,
                    const float* __restrict__ mod_w,
                    const float* __restrict__ mod_b)
{
    __shared__ __align__(16) float sw[16 * 576];
    __shared__ __align__(16) float sp[2][4 * SPA];
    __shared__ float sb[16];

    const int tx = threadIdx.x, ty = threadIdx.y;
    const int tid = ty * 16 + tx;
    const int bz = blockIdx.z;
    const int b = bz >> 1, half = bz & 1;
    const int base = half * 16;
    const int count = half ? 11 : 16;
    const int bx = blockIdx.x * LTW, by = blockIdx.y * LTH;
    const int x0 = bx + tx * 4, y = by + ty;

    for (int i = tid; i < 16 * 576; i += 256) {
        int lo = i / 576, rest = i - lo * 576;
        int oc = base + lo;
        float v = 0.f;
        if (oc < 18) v = off_w[(size_t)oc * 576 + rest];
        else if (oc < 27) v = mod_w[(size_t)(oc - 18) * 576 + rest];
        sw[rest * 16 + lo] = v;
    }
    if (tid < 16) {
        int oc = base + tid;
        sb[tid] = (oc < 18) ? off_b[oc] : (oc < 27 ? mod_b[oc - 18] : 0.f);
    }

    const float* xb = g_hs + (size_t)b * CIN_D * HW;

    #pragma unroll
    for (int cc = 0; cc < 4; cc++)
        stage_patch_async(sp[0] + cc * SPA, xb + (size_t)cc * HW, bx, by, tid);
    CP_COMMIT();

    __syncthreads();

    ull acc2[8][4];
    #pragma unroll
    for (int q = 0; q < 8; q++) {
        ull bv = pack2(sb[2*q], sb[2*q+1]);
        #pragma unroll
        for (int px = 0; px < 4; px++) acc2[q][px] = bv;
    }

    for (int cb = 0; cb < 16; cb++) {
        int cur = cb & 1;
        CP_WAIT0();
        __syncthreads();
        if (cb + 1 < 16) {
            int cn = (cb + 1) * 4;
            #pragma unroll
            for (int cc = 0; cc < 4; cc++)
                stage_patch_async(sp[cur ^ 1] + cc * SPA, xb + (size_t)(cn + cc) * HW, bx, by, tid);
        }
        CP_COMMIT();
        int c0 = cb * 4;
        #pragma unroll
        for (int cc = 0; cc < 4; cc++)
            conv_accum_p(acc2, sp[cur] + cc * SPA, sw + (c0 + cc) * 144, tx, ty);
    }

    if (y < Hh) {
        const int p = y * Ww + x0;
        #pragma unroll
        for (int lo = 0; lo < 16; lo++) {
            if (lo >= count) break;
            int oc = base + lo;
            float o4[4];
            #pragma unroll
            for (int px = 0; px < 4; px++) {
                float2 u = unpack2(acc2[lo >> 1][px]);
                o4[px] = (lo & 1) ? u.y : u.x;
            }
            if (oc >= 18) {
                #pragma unroll
                for (int px = 0; px < 4; px++) o4[px] = 2.f * sig_(o4[px]);
            }
            *(float4*)(g_om + ((size_t)b * 27 + oc) * HW + p) = *(float4*)o4;
        }
    }
}

// ---------------------------------------------------------------------------
// Modulated deformable conv. block (32,8), 1 px/thread, 16 outputs (8 pairs).
// ---------------------------------------------------------------------------
__global__ __launch_bounds__(256)
void deform_kernel(const float* __restrict__ def_w,
                   const float* __restrict__ def_b)
{
    __shared__ __align__(16) float swd[NK * CIN_D * 9];
    __shared__ float sb[NK];

    const int bx = blockIdx.x * 32, by = blockIdx.y * 8;
    const int b = blockIdx.z;
    const int tx = threadIdx.x, ty = threadIdx.y;
    const int tid = ty * 32 + tx;

    for (int i = tid; i < NK * CIN_D * 9; i += 256) {
        int o = i / 576, rest = i - o * 576;
        swd[rest * 16 + o] = def_w[i];
    }
    if (tid < NK) sb[tid] = def_b[tid];
    __syncthreads();

    const int x = bx + tx, y = by + ty;
    if (y >= Hh) return;
    const int p = y * Ww + x;

    const float* xb = g_hs + (size_t)b * CIN_D * HW;
    const float* om = g_om + (size_t)b * 27 * HW;

    ull acc2[8];
    #pragma unroll
    for (int q = 0; q < 8; q++) acc2[q] = pack2(sb[2*q], sb[2*q+1]);

    #pragma unroll
    for (int j = 0; j < 9; j++) {
        int ky = j / 3, kx = j - ky * 3;
        float dy = om[(2 * j) * HW + p];
        float dx = om[(2 * j + 1) * HW + p];
        float m  = om[(18 + j) * HW + p];
        float py = (float)(y - 1 + ky) + dy;
        float px_ = (float)(x - 1 + kx) + dx;
        float y0f = floorf(py), x0f = floorf(px_);
        float wy = py - y0f, wx = px_ - x0f;
        int y0 = (int)y0f, x0 = (int)x0f;
        int y1 = y0 + 1,   x1 = x0 + 1;
        float vy0 = (y0 >= 0 && y0 < Hh) ? 1.f : 0.f;
        float vy1 = (y1 >= 0 && y1 < Hh) ? 1.f : 0.f;
        float vx0 = (x0 >= 0 && x0 < Ww) ? 1.f : 0.f;
        float vx1 = (x1 >= 0 && x1 < Ww) ? 1.f : 0.f;
        int y0c = min(max(y0, 0), Hh - 1), y1c = min(max(y1, 0), Hh - 1);
        int x0c = min(max(x0, 0), Ww - 1), x1c = min(max(x1, 0), Ww - 1);
        float w00 = (1.f - wy) * (1.f - wx) * vy0 * vx0 * m;
        float w01 = (1.f - wy) * wx         * vy0 * vx1 * m;
        float w10 = wy * (1.f - wx)         * vy1 * vx0 * m;
        float w11 = wy * wx                 * vy1 * vx1 * m;
        int o00 = y0c * Ww + x0c, o01 = y0c * Ww + x1c;
        int o10 = y1c * Ww + x0c, o11 = y1c * Ww + x1c;

        #pragma unroll 4
        for (int c = 0; c < CIN_D; c++) {
            const float* pc_ = xb + (size_t)c * HW;
            float s = w00 * pc_[o00] + w01 * pc_[o01]
                    + w10 * pc_[o10] + w11 * pc_[o11];
            ull ss = pack2(s, s);
            const ulonglong2* w2 = (const ulonglong2*)(swd + (c * 9 + j) * 16);
            ulonglong2 wa = w2[0], wb = w2[1], wc2 = w2[2], wd = w2[3];
            ffma2(acc2[0], ss, wa.x); ffma2(acc2[1], ss, wa.y);
            ffma2(acc2[2], ss, wb.x); ffma2(acc2[3], ss, wb.y);
            ffma2(acc2[4], ss, wc2.x); ffma2(acc2[5], ss, wc2.y);
            ffma2(acc2[6], ss, wd.x); ffma2(acc2[7], ss, wd.y);
        }
    }

    #pragma unroll
    for (int q = 0; q < 8; q++) {
        float2 u = unpack2(acc2[q]);
        g_def[((size_t)b * NK + 2*q    ) * HW + p] = u.x;
        g_def[((size_t)b * NK + 2*q + 1) * HW + p] = u.y;
    }
}

// ---------------------------------------------------------------------------
// Output conv 16 -> 48 (3 groups of 16) + pixel shuffle + clip. pair f32x2.
// ---------------------------------------------------------------------------
__global__ __launch_bounds__(256, 2)
void outconv_kernel(const float* __restrict__ out_w,
                    const float* __restrict__ out_b,
                    float* __restrict__ out)
{
    __shared__ __align__(16) float sw[16 * 144];
    __shared__ __align__(16) float sp[2][4 * SPA];
    __shared__ float sb[16];

    const int tx = threadIdx.x, ty = threadIdx.y;
    const int tid = ty * 16 + tx;
    const int bz = blockIdx.z;
    const int b = bz / 3, g3 = bz - b * 3;
    const int base = g3 * 16;
    const int bx = blockIdx.x * LTW, by = blockIdx.y * LTH;
    const int x0 = bx + tx * 4, y = by + ty;

    for (int i = tid; i < 16 * 144; i += 256) {
        int lo = i / 144, rest = i - lo * 144;
        sw[rest * 16 + lo] = out_w[(size_t)(base + lo) * 144 + rest];
    }
    if (tid < 16) sb[tid] = out_b[base + tid];

    const float* xb = g_def + (size_t)b * NK * HW;

    #pragma unroll
    for (int cc = 0; cc < 4; cc++)
        stage_patch_async(sp[0] + cc * SPA, xb + (size_t)cc * HW, bx, by, tid);
    CP_COMMIT();

    __syncthreads();

    ull acc2[8][4];
    #pragma unroll
    for (int q = 0; q < 8; q++) {
        ull bv = pack2(sb[2*q], sb[2*q+1]);
        #pragma unroll
        for (int px = 0; px < 4; px++) acc2[q][px] = bv;
    }

    for (int cb = 0; cb < 4; cb++) {
        int cur = cb & 1;
        CP_WAIT0();
        __syncthreads();
        if (cb + 1 < 4) {
            int cn = (cb + 1) * 4;
            #pragma unroll
            for (int cc = 0; cc < 4; cc++)
                stage_patch_async(sp[cur ^ 1] + cc * SPA, xb + (size_t)(cn + cc) * HW, bx, by, tid);
        }
        CP_COMMIT();
        int c0 = cb * 4;
        #pragma unroll
        for (int cc = 0; cc < 4; cc++)
            conv_accum_p(acc2, sp[cur] + cc * SPA, sw + (c0 + cc) * 144, tx, ty);
    }

    if (y < Hh) {
        #pragma unroll
        for (int lo = 0; lo < 16; lo++) {
            int oc = base + lo;
            int cch = oc >> 4, rem = oc & 15;
            int r1 = rem >> 2, r2 = rem & 3;
            #pragma unroll
            for (int px = 0; px < 4; px++) {
                float2 u = unpack2(acc2[lo >> 1][px]);
                float val = (lo & 1) ? u.y : u.x;
                val = fminf(fmaxf(val, 0.f), 255.f);
                size_t oi = (((size_t)b * NC + cch) * (Hh * SCALE) + (y * SCALE + r1))
                            * (size_t)(Ww * SCALE) + ((x0 + px) * SCALE + r2);
                out[oi] = val;
            }
        }
    }
}

// ---------------------------------------------------------------------------
extern "C" void kernel_launch(void* const* d_in, const int* in_sizes, int n_in,
                              void* d_out, int out_size)
{
    const float* X      = (const float*)d_in[0];
    const float* lstm_w = (const float*)d_in[1];
    const float* lstm_b = (const float*)d_in[2];
    const float* W_ci   = (const float*)d_in[3];
    const float* W_cf   = (const float*)d_in[4];
    const float* W_co   = (const float*)d_in[5];
    const float* off_w  = (const float*)d_in[6];
    const float* off_b  = (const float*)d_in[7];
    const float* mod_w  = (const float*)d_in[8];
    const float* mod_b  = (const float*)d_in[9];
    const float* def_w  = (const float*)d_in[10];
    const float* def_b  = (const float*)d_in[11];
    const float* out_w  = (const float*)d_in[12];
    const float* out_b  = (const float*)d_in[13];
    float* out = (float*)d_out;

    dim3 blk16(16, 16);
    dim3 grid_lstm(Ww / LTW, (Hh + LTH - 1) / LTH, Bn * 4);
    dim3 grid_om(Ww / LTW, (Hh + LTH - 1) / LTH, Bn * 2);
    dim3 grid_oc(Ww / LTW, (Hh + LTH - 1) / LTH, Bn * 3);

    for (int t = 0; t < Tt; t++)
        lstm_step_kernel<<<grid_lstm, blk16>>>(X, lstm_w, lstm_b, W_ci, W_cf, W_co, t);

    offmask_kernel<<<grid_om, blk16>>>(off_w, off_b, mod_w, mod_b);

    dim3 blk32(32, 8);
    dim3 grid_def(Ww / 32, (Hh + 7) / 8, Bn);
    deform_kernel<<<grid_def, blk32>>>(def_w, def_b);

    outconv_kernel<<<grid_oc, blk16>>>(out_w, out_b, out);
}

// round 8
// speedup vs baseline: 1.1589x; 1.0534x over previous
#include <cuda_runtime.h>
#include <math.h>

#define Bn 2
#define Tt 4
#define NC 3
#define NK 16
#define Hh 180
#define Ww 320
#define HW (Hh*Ww)
#define CIN_D (Tt*NK)   // 64
#define OUT_C 48
#define SCALE 4

#define LTW 64
#define LTH 16
#define SPW 72          // patch stride: gx in [bx-4, bx+68), 16B-aligned staging
#define SPH 18
#define SPA (SPH*SPW)   // 1296 floats
#define SPF (SPH*18)    // float4 slots per patch

typedef unsigned long long ull;

// Scratch (no cudaMalloc allowed)
__device__ float g_hs[Bn*CIN_D*HW];
__device__ float g_c[Bn*NK*HW];
__device__ float g_om[Bn*27*HW];
__device__ float g_def[Bn*NK*HW];

__device__ __forceinline__ float sig_(float v) {
    return __fdividef(1.f, 1.f + __expf(-v));
}
__device__ __forceinline__ float tanh_(float v) {
    float e = __expf(2.f * v);
    return 1.f - __fdividef(2.f, e + 1.f);
}

// ---- packed f32x2 helpers ----
__device__ __forceinline__ ull pack2(float lo, float hi) {
    ull r;
    asm("mov.b64 %0, {%1, %2};" : "=l"(r) : "f"(lo), "f"(hi));
    return r;
}
__device__ __forceinline__ void ffma2(ull& d, ull a, ull b) {
    asm("fma.rn.f32x2 %0, %1, %2, %0;" : "+l"(d) : "l"(a), "l"(b));
}
__device__ __forceinline__ float2 unpack2(ull v) {
    float2 f;
    asm("mov.b64 {%0, %1}, %2;" : "=f"(f.x), "=f"(f.y) : "l"(v));
    return f;
}

__device__ __forceinline__ void cp_async16(float* dst_smem, const float* src) {
    unsigned d = (unsigned)__cvta_generic_to_shared(dst_smem);
    asm volatile("cp.async.cg.shared.global [%0], [%1], 16;" :: "r"(d), "l"(src));
}
#define CP_COMMIT() asm volatile("cp.async.commit_group;" ::: "memory")
#define CP_WAIT0()  asm volatile("cp.async.wait_group 0;" ::: "memory")

// stage one channel patch with 16B cp.async. Covers gx in [bx-4, bx+68).
// f=0 zeroed iff bx==0 (left pad); f=17 zeroed iff bx+68>Ww (right pad, and
// col 68 = gx bx+64 = Ww must be zero there anyway). Vertical OOB rows zeroed.
__device__ __forceinline__ void stage_patch16(float* dst, const float* src,
                                              int bx, int by, int tid)
{
    #pragma unroll
    for (int i = tid; i < SPF; i += 256) {
        int pr = i / 18, f = i - pr * 18;
        int gy = by - 1 + pr;
        int gxf = bx - 4 + f * 4;
        float* d = dst + pr * SPW + f * 4;
        if (gy >= 0 && gy < Hh && gxf >= 0 && gxf + 4 <= Ww)
            cp_async16(d, src + gy * Ww + gxf);
        else
            *(float4*)d = make_float4(0.f, 0.f, 0.f, 0.f);
    }
}

// one channel's 3x3 conv; acc2[q][px] = outputs (2q,2q+1) at pixel px.
// Patch cols used: tx*4+3 .. tx*4+8 (gx = x-1 .. x+4). 8B-aligned float2 reads.
__device__ __forceinline__ void conv_accum_p(ull acc2[8][4], const float* patch,
                                             const float* wc, int tx, int ty)
{
    #pragma unroll
    for (int tr = 0; tr < 3; tr++) {
        const float2* rp = (const float2*)(patch + (ty + tr) * SPW + tx * 4 + 2);
        float2 a = rp[0], b = rp[1], c = rp[2], d = rp[3];
        float v[6] = {a.y, b.x, b.y, c.x, c.y, d.x};
        ull vv[6];
        #pragma unroll
        for (int j = 0; j < 6; j++) vv[j] = pack2(v[j], v[j]);
        #pragma unroll
        for (int tc = 0; tc < 3; tc++) {
            const ulonglong2* w2 = (const ulonglong2*)(wc + (tr * 3 + tc) * 16);
            ulonglong2 wa = w2[0], wb = w2[1], wcq = w2[2], wd = w2[3];
            ull wp[8] = {wa.x, wa.y, wb.x, wb.y, wcq.x, wcq.y, wd.x, wd.y};
            #pragma unroll
            for (int q = 0; q < 8; q++) {
                #pragma unroll
                for (int px = 0; px < 4; px++)
                    ffma2(acc2[q][px], vv[tc + px], wp[q]);
            }
        }
    }
}

// ---------------------------------------------------------------------------
// ConvLSTM step. block (16,16); thread = 4 px, 16 outputs (4 k x 4 gates)
// blockIdx.z = b*4 + kg. cp.async.16 pipelined, CH=4, f32x2 output pairs.
// ---------------------------------------------------------------------------
__global__ __launch_bounds__(256, 2)
void lstm_step_kernel(const float* __restrict__ X,
                      const float* __restrict__ lw,
                      const float* __restrict__ lb,
                      const float* __restrict__ Wci,
                      const float* __restrict__ Wcf,
                      const float* __restrict__ Wco,
                      int t)
{
    __shared__ __align__(16) float sw[19 * 9 * 16];
    __shared__ __align__(16) float sp[2][4 * SPA];
    __shared__ float sb[16];

    const int tx = threadIdx.x, ty = threadIdx.y;
    const int tid = ty * 16 + tx;
    const int bz = blockIdx.z;
    const int b = bz >> 2, kg = bz & 3;
    const int bx = blockIdx.x * LTW, by = blockIdx.y * LTH;
    const int x0 = bx + tx * 4, y = by + ty;

    for (int i = tid; i < 19 * 144; i += 256) {
        int lo = i / 171, rest = i - lo * 171;
        int row = (lo >> 2) * NK + kg * 4 + (lo & 3);
        sw[rest * 16 + lo] = lw[row * 171 + rest];
    }
    if (tid < 16)
        sb[tid] = lb[(tid >> 2) * NK + kg * 4 + (tid & 3)];

    const int ncin = (t == 0) ? NC : (NC + NK);
    const int nb = (ncin + 3) >> 2;

    #define LSTM_SRC(c) ((c) < NC \
        ? (X + (((size_t)b * Tt + t) * NC + (c)) * HW) \
        : (g_hs + ((size_t)b * CIN_D + (t - 1) * NK + ((c) - NC)) * HW))

    #pragma unroll
    for (int cc = 0; cc < 4; cc++)
        if (cc < ncin) stage_patch16(sp[0] + cc * SPA, LSTM_SRC(cc), bx, by, tid);
    CP_COMMIT();

    __syncthreads();   // sb/sw visible

    ull acc2[8][4];
    #pragma unroll
    for (int q = 0; q < 8; q++) {
        ull bv = pack2(sb[2*q], sb[2*q+1]);
        #pragma unroll
        for (int px = 0; px < 4; px++) acc2[q][px] = bv;
    }

    for (int cb = 0; cb < nb; cb++) {
        int cur = cb & 1;
        CP_WAIT0();
        __syncthreads();
        if (cb + 1 < nb) {
            int cn = (cb + 1) * 4;
            #pragma unroll
            for (int cc = 0; cc < 4; cc++)
                if (cn + cc < ncin)
                    stage_patch16(sp[cur ^ 1] + cc * SPA, LSTM_SRC(cn + cc), bx, by, tid);
        }
        CP_COMMIT();
        int c0 = cb * 4;
        #pragma unroll
        for (int cc = 0; cc < 4; cc++)
            if (c0 + cc < ncin)
                conv_accum_p(acc2, sp[cur] + cc * SPA, sw + (c0 + cc) * 144, tx, ty);
    }
    #undef LSTM_SRC

    if (y < Hh) {
        const int p = y * Ww + x0;
        float accf[16][4];
        #pragma unroll
        for (int q = 0; q < 8; q++) {
            #pragma unroll
            for (int px = 0; px < 4; px++) {
                float2 u = unpack2(acc2[q][px]);
                accf[2*q][px] = u.x;
                accf[2*q+1][px] = u.y;
            }
        }
        #pragma unroll
        for (int kk = 0; kk < 4; kk++) {
            int k = kg * 4 + kk;
            float ci4[4], cf4[4], co4[4], cp4[4], cn4[4], h4[4];
            *(float4*)ci4 = *(const float4*)(Wci + k * HW + p);
            *(float4*)cf4 = *(const float4*)(Wcf + k * HW + p);
            *(float4*)co4 = *(const float4*)(Wco + k * HW + p);
            if (t == 0) {
                #pragma unroll
                for (int px = 0; px < 4; px++) cp4[px] = 0.f;
            } else {
                *(float4*)cp4 = *(const float4*)(g_c + ((size_t)b * NK + k) * HW + p);
            }
            #pragma unroll
            for (int px = 0; px < 4; px++) {
                float cprev = cp4[px];
                float i_ = sig_(accf[kk][px]      + ci4[px] * cprev);
                float f_ = sig_(accf[4 + kk][px]  + cf4[px] * cprev);
                float cn = f_ * cprev + i_ * tanh_(accf[8 + kk][px]);
                float o_ = sig_(accf[12 + kk][px] + co4[px] * cn);
                cn4[px] = cn;
                h4[px] = o_ * tanh_(cn);
            }
            *(float4*)(g_c + ((size_t)b * NK + k) * HW + p) = *(float4*)cn4;
            *(float4*)(g_hs + ((size_t)b * CIN_D + t * NK + k) * HW + p) = *(float4*)h4;
        }
    }
}

// ---------------------------------------------------------------------------
// Offset+mask conv 64 -> 27. blockIdx.z = b*2 + half.
// ---------------------------------------------------------------------------
__global__ __launch_bounds__(256, 2)
void offmask_kernel(const float* __restrict__ off_w,
                    const float* __restrict__ off_b,
                    const float* __restrict__ mod_w,
                    const float* __restrict__ mod_b)
{
    __shared__ __align__(16) float sw[16 * 576];
    __shared__ __align__(16) float sp[2][4 * SPA];
    __shared__ float sb[16];

    const int tx = threadIdx.x, ty = threadIdx.y;
    const int tid = ty * 16 + tx;
    const int bz = blockIdx.z;
    const int b = bz >> 1, half = bz & 1;
    const int base = half * 16;
    const int count = half ? 11 : 16;
    const int bx = blockIdx.x * LTW, by = blockIdx.y * LTH;
    const int x0 = bx + tx * 4, y = by + ty;

    for (int i = tid; i < 16 * 576; i += 256) {
        int lo = i / 576, rest = i - lo * 576;
        int oc = base + lo;
        float v = 0.f;
        if (oc < 18) v = off_w[(size_t)oc * 576 + rest];
        else if (oc < 27) v = mod_w[(size_t)(oc - 18) * 576 + rest];
        sw[rest * 16 + lo] = v;
    }
    if (tid < 16) {
        int oc = base + tid;
        sb[tid] = (oc < 18) ? off_b[oc] : (oc < 27 ? mod_b[oc - 18] : 0.f);
    }

    const float* xb = g_hs + (size_t)b * CIN_D * HW;

    #pragma unroll
    for (int cc = 0; cc < 4; cc++)
        stage_patch16(sp[0] + cc * SPA, xb + (size_t)cc * HW, bx, by, tid);
    CP_COMMIT();

    __syncthreads();

    ull acc2[8][4];
    #pragma unroll
    for (int q = 0; q < 8; q++) {
        ull bv = pack2(sb[2*q], sb[2*q+1]);
        #pragma unroll
        for (int px = 0; px < 4; px++) acc2[q][px] = bv;
    }

    for (int cb = 0; cb < 16; cb++) {
        int cur = cb & 1;
        CP_WAIT0();
        __syncthreads();
        if (cb + 1 < 16) {
            int cn = (cb + 1) * 4;
            #pragma unroll
            for (int cc = 0; cc < 4; cc++)
                stage_patch16(sp[cur ^ 1] + cc * SPA, xb + (size_t)(cn + cc) * HW, bx, by, tid);
        }
        CP_COMMIT();
        int c0 = cb * 4;
        #pragma unroll
        for (int cc = 0; cc < 4; cc++)
            conv_accum_p(acc2, sp[cur] + cc * SPA, sw + (c0 + cc) * 144, tx, ty);
    }

    if (y < Hh) {
        const int p = y * Ww + x0;
        #pragma unroll
        for (int lo = 0; lo < 16; lo++) {
            if (lo >= count) break;
            int oc = base + lo;
            float o4[4];
            #pragma unroll
            for (int px = 0; px < 4; px++) {
                float2 u = unpack2(acc2[lo >> 1][px]);
                o4[px] = (lo & 1) ? u.y : u.x;
            }
            if (oc >= 18) {
                #pragma unroll
                for (int px = 0; px < 4; px++) o4[px] = 2.f * sig_(o4[px]);
            }
            *(float4*)(g_om + ((size_t)b * 27 + oc) * HW + p) = *(float4*)o4;
        }
    }
}

// ---------------------------------------------------------------------------
// Modulated deformable conv. block (32,8), 1 px/thread, 16 outputs (8 pairs).
// ---------------------------------------------------------------------------
__global__ __launch_bounds__(256)
void deform_kernel(const float* __restrict__ def_w,
                   const float* __restrict__ def_b)
{
    __shared__ __align__(16) float swd[NK * CIN_D * 9];
    __shared__ float sb[NK];

    const int bx = blockIdx.x * 32, by = blockIdx.y * 8;
    const int b = blockIdx.z;
    const int tx = threadIdx.x, ty = threadIdx.y;
    const int tid = ty * 32 + tx;

    for (int i = tid; i < NK * CIN_D * 9; i += 256) {
        int o = i / 576, rest = i - o * 576;
        swd[rest * 16 + o] = def_w[i];
    }
    if (tid < NK) sb[tid] = def_b[tid];
    __syncthreads();

    const int x = bx + tx, y = by + ty;
    if (y >= Hh) return;
    const int p = y * Ww + x;

    const float* xb = g_hs + (size_t)b * CIN_D * HW;
    const float* om = g_om + (size_t)b * 27 * HW;

    ull acc2[8];
    #pragma unroll
    for (int q = 0; q < 8; q++) acc2[q] = pack2(sb[2*q], sb[2*q+1]);

    #pragma unroll
    for (int j = 0; j < 9; j++) {
        int ky = j / 3, kx = j - ky * 3;
        float dy = om[(2 * j) * HW + p];
        float dx = om[(2 * j + 1) * HW + p];
        float m  = om[(18 + j) * HW + p];
        float py = (float)(y - 1 + ky) + dy;
        float px_ = (float)(x - 1 + kx) + dx;
        float y0f = floorf(py), x0f = floorf(px_);
        float wy = py - y0f, wx = px_ - x0f;
        int y0 = (int)y0f, x0 = (int)x0f;
        int y1 = y0 + 1,   x1 = x0 + 1;
        float vy0 = (y0 >= 0 && y0 < Hh) ? 1.f : 0.f;
        float vy1 = (y1 >= 0 && y1 < Hh) ? 1.f : 0.f;
        float vx0 = (x0 >= 0 && x0 < Ww) ? 1.f : 0.f;
        float vx1 = (x1 >= 0 && x1 < Ww) ? 1.f : 0.f;
        int y0c = min(max(y0, 0), Hh - 1), y1c = min(max(y1, 0), Hh - 1);
        int x0c = min(max(x0, 0), Ww - 1), x1c = min(max(x1, 0), Ww - 1);
        float w00 = (1.f - wy) * (1.f - wx) * vy0 * vx0 * m;
        float w01 = (1.f - wy) * wx         * vy0 * vx1 * m;
        float w10 = wy * (1.f - wx)         * vy1 * vx0 * m;
        float w11 = wy * wx                 * vy1 * vx1 * m;
        int o00 = y0c * Ww + x0c, o01 = y0c * Ww + x1c;
        int o10 = y1c * Ww + x0c, o11 = y1c * Ww + x1c;

        #pragma unroll 4
        for (int c = 0; c < CIN_D; c++) {
            const float* pc_ = xb + (size_t)c * HW;
            float s = w00 * pc_[o00] + w01 * pc_[o01]
                    + w10 * pc_[o10] + w11 * pc_[o11];
            ull ss = pack2(s, s);
            const ulonglong2* w2 = (const ulonglong2*)(swd + (c * 9 + j) * 16);
            ulonglong2 wa = w2[0], wb = w2[1], wc2 = w2[2], wd = w2[3];
            ffma2(acc2[0], ss, wa.x); ffma2(acc2[1], ss, wa.y);
            ffma2(acc2[2], ss, wb.x); ffma2(acc2[3], ss, wb.y);
            ffma2(acc2[4], ss, wc2.x); ffma2(acc2[5], ss, wc2.y);
            ffma2(acc2[6], ss, wd.x); ffma2(acc2[7], ss, wd.y);
        }
    }

    #pragma unroll
    for (int q = 0; q < 8; q++) {
        float2 u = unpack2(acc2[q]);
        g_def[((size_t)b * NK + 2*q    ) * HW + p] = u.x;
        g_def[((size_t)b * NK + 2*q + 1) * HW + p] = u.y;
    }
}

// ---------------------------------------------------------------------------
// Output conv 16 -> 48 (3 groups of 16) + pixel shuffle + clip.
// ---------------------------------------------------------------------------
__global__ __launch_bounds__(256, 2)
void outconv_kernel(const float* __restrict__ out_w,
                    const float* __restrict__ out_b,
                    float* __restrict__ out)
{
    __shared__ __align__(16) float sw[16 * 144];
    __shared__ __align__(16) float sp[2][4 * SPA];
    __shared__ float sb[16];

    const int tx = threadIdx.x, ty = threadIdx.y;
    const int tid = ty * 16 + tx;
    const int bz = blockIdx.z;
    const int b = bz / 3, g3 = bz - b * 3;
    const int base = g3 * 16;
    const int bx = blockIdx.x * LTW, by = blockIdx.y * LTH;
    const int x0 = bx + tx * 4, y = by + ty;

    for (int i = tid; i < 16 * 144; i += 256) {
        int lo = i / 144, rest = i - lo * 144;
        sw[rest * 16 + lo] = out_w[(size_t)(base + lo) * 144 + rest];
    }
    if (tid < 16) sb[tid] = out_b[base + tid];

    const float* xb = g_def + (size_t)b * NK * HW;

    #pragma unroll
    for (int cc = 0; cc < 4; cc++)
        stage_patch16(sp[0] + cc * SPA, xb + (size_t)cc * HW, bx, by, tid);
    CP_COMMIT();

    __syncthreads();

    ull acc2[8][4];
    #pragma unroll
    for (int q = 0; q < 8; q++) {
        ull bv = pack2(sb[2*q], sb[2*q+1]);
        #pragma unroll
        for (int px = 0; px < 4; px++) acc2[q][px] = bv;
    }

    for (int cb = 0; cb < 4; cb++) {
        int cur = cb & 1;
        CP_WAIT0();
        __syncthreads();
        if (cb + 1 < 4) {
            int cn = (cb + 1) * 4;
            #pragma unroll
            for (int cc = 0; cc < 4; cc++)
                stage_patch16(sp[cur ^ 1] + cc * SPA, xb + (size_t)(cn + cc) * HW, bx, by, tid);
        }
        CP_COMMIT();
        int c0 = cb * 4;
        #pragma unroll
        for (int cc = 0; cc < 4; cc++)
            conv_accum_p(acc2, sp[cur] + cc * SPA, sw + (c0 + cc) * 144, tx, ty);
    }

    if (y < Hh) {
        #pragma unroll
        for (int lo = 0; lo < 16; lo++) {
            int oc = base + lo;
            int cch = oc >> 4, rem = oc & 15;
            int r1 = rem >> 2, r2 = rem & 3;
            #pragma unroll
            for (int px = 0; px < 4; px++) {
                float2 u = unpack2(acc2[lo >> 1][px]);
                float val = (lo & 1) ? u.y : u.x;
                val = fminf(fmaxf(val, 0.f), 255.f);
                size_t oi = (((size_t)b * NC + cch) * (Hh * SCALE) + (y * SCALE + r1))
                            * (size_t)(Ww * SCALE) + ((x0 + px) * SCALE + r2);
                out[oi] = val;
            }
        }
    }
}

// ---------------------------------------------------------------------------
extern "C" void kernel_launch(void* const* d_in, const int* in_sizes, int n_in,
                              void* d_out, int out_size)
{
    const float* X      = (const float*)d_in[0];
    const float* lstm_w = (const float*)d_in[1];
    const float* lstm_b = (const float*)d_in[2];
    const float* W_ci   = (const float*)d_in[3];
    const float* W_cf   = (const float*)d_in[4];
    const float* W_co   = (const float*)d_in[5];
    const float* off_w  = (const float*)d_in[6];
    const float* off_b  = (const float*)d_in[7];
    const float* mod_w  = (const float*)d_in[8];
    const float* mod_b  = (const float*)d_in[9];
    const float* def_w  = (const float*)d_in[10];
    const float* def_b  = (const float*)d_in[11];
    const float* out_w  = (const float*)d_in[12];
    const float* out_b  = (const float*)d_in[13];
    float* out = (float*)d_out;

    dim3 blk16(16, 16);
    dim3 grid_lstm(Ww / LTW, (Hh + LTH - 1) / LTH, Bn * 4);
    dim3 grid_om(Ww / LTW, (Hh + LTH - 1) / LTH, Bn * 2);
    dim3 grid_oc(Ww / LTW, (Hh + LTH - 1) / LTH, Bn * 3);

    for (int t = 0; t < Tt; t++)
        lstm_step_kernel<<<grid_lstm, blk16>>>(X, lstm_w, lstm_b, W_ci, W_cf, W_co, t);

    offmask_kernel<<<grid_om, blk16>>>(off_w, off_b, mod_w, mod_b);

    dim3 blk32(32, 8);
    dim3 grid_def(Ww / 32, (Hh + 7) / 8, Bn);
    deform_kernel<<<grid_def, blk32>>>(def_w, def_b);

    outconv_kernel<<<grid_oc, blk16>>>(out_w, out_b, out);
}